// round 12
// baseline (speedup 1.0000x reference)
#include <cuda_runtime.h>
#include <cuda_fp16.h>
#include <cstdint>

#define NN 50000
#define EE 800000
#define CC 128
#define LL 3
#define KK 10

#define LOG2E 1.4426950408889634f
#define MSCALE 0.34657359027997264f  // 0.5 * ln2

// ---------------- scratch ----------------
__device__ __align__(16) float  g_h[NN * CC];
__device__ __align__(16) __half g_Ti[(size_t)NN * 256];       // interleaved [hf_i x4 | hs_i x4]
__device__ __align__(16) __half g_Tj[(size_t)NN * 256];       // interleaved [hf_j x4 | hs_j x4]
__device__ __align__(16) __half g_Bcath[LL * 512 * CC];       // prescaled half weight rows
__device__ __align__(16) float  g_AfT[LL * 6 * CC];           // x0.5
__device__ __align__(16) float  g_AsT[LL * 6 * CC];           // xlog2e
__device__ __align__(16) float  g_cf[LL * CC];
__device__ __align__(16) float  g_cs[LL * CC];
__device__ int   g_deg[NN + 1];
__device__ int   g_off[NN + 1];
__device__ int   g_cur[NN];
__device__ __align__(16) uint4 g_edge[EE];  // {src, ea01, ea23, ea45}
__device__ int   g_bsum[64];

// ---------------- math helpers ----------------
__device__ __forceinline__ float ex2f(float x) {
    float r; asm("ex2.approx.f32 %0, %1;" : "=f"(r) : "f"(x)); return r;
}
__device__ __forceinline__ float lg2f(float x) {
    float r; asm("lg2.approx.f32 %0, %1;" : "=f"(r) : "f"(x)); return r;
}
__device__ __forceinline__ half2 h2tanh_(half2 x) {
    uint32_t xi = *(uint32_t*)&x, ri;
    asm("tanh.approx.f16x2 %0, %1;" : "=r"(ri) : "r"(xi));
    return *(half2*)&ri;
}
__device__ __forceinline__ void mma_f16(float* d, const uint32_t* a, const uint32_t* b) {
    asm volatile(
        "mma.sync.aligned.m16n8k16.row.col.f32.f16.f16.f32 "
        "{%0,%1,%2,%3}, {%4,%5,%6,%7}, {%8,%9}, {%0,%1,%2,%3};"
        : "+f"(d[0]), "+f"(d[1]), "+f"(d[2]), "+f"(d[3])
        : "r"(a[0]), "r"(a[1]), "r"(a[2]), "r"(a[3]), "r"(b[0]), "r"(b[1]));
}
#define CP_COMMIT() asm volatile("cp.async.commit_group;")
#define CP_WAIT1()  asm volatile("cp.async.wait_group 1;")
#define CP_WAIT0()  asm volatile("cp.async.wait_group 0;")

// ---------------- zero degree (fork stream) ----------------
__global__ void k_zero() {
    int i = blockIdx.x * blockDim.x + threadIdx.x;
    if (i <= NN) g_deg[i] = 0;
}

// ---------------- fused setup: fold | bprep(half) | node_encode ----------------
#define FB 21
#define WB 768
#define NB 25000
__global__ void k_setup(const float* __restrict__ x, const float* __restrict__ nW,
                        const float* __restrict__ nb,
                        const float* __restrict__ Wf, const float* __restrict__ bf,
                        const float* __restrict__ Ws, const float* __restrict__ bs,
                        const float* __restrict__ eW, const float* __restrict__ eb) {
    int b = blockIdx.x, tid = threadIdx.x;
    if (b < FB) {
        int t = b * 256 + tid;
        if (t >= LL * CC * 14) return;
        int l = t / (CC * 14);
        int r = t % (CC * 14);
        int c = r / 14, kk = r % 14;
        const float* rf = Wf + ((size_t)(l * CC + c) * 3 * CC) + 2 * CC;
        const float* rs = Ws + ((size_t)(l * CC + c) * 3 * CC) + 2 * CC;
        if (kk < 6) {
            float s = 0.f;
            for (int j = 0; j < CC; j++) s = fmaf(rf[j], eW[j * 6 + kk], s);
            g_AfT[l * 6 * CC + kk * CC + c] = s * 0.5f;
        } else if (kk < 12) {
            int k = kk - 6;
            float s = 0.f;
            for (int j = 0; j < CC; j++) s = fmaf(rs[j], eW[j * 6 + k], s);
            g_AsT[l * 6 * CC + k * CC + c] = s * LOG2E;
        } else if (kk == 12) {
            float s = bf[l * CC + c];
            for (int j = 0; j < CC; j++) s = fmaf(rf[j], eb[j], s);
            g_cf[l * CC + c] = s * 0.5f;
        } else {
            float s = bs[l * CC + c];
            for (int j = 0; j < CC; j++) s = fmaf(rs[j], eb[j], s);
            g_cs[l * CC + c] = s * LOG2E;
        }
    } else if (b < FB + WB) {
        int t = (b - FB) * 256 + tid;
        int l = t / (512 * CC);
        int r = t % (512 * CC);
        int n = r / CC, k = r % CC;
        int q = n >> 7, c = n & 127;
        const float* base = (q < 2 ? Wf : Ws);
        float scale = (q < 2) ? 0.5f : LOG2E;
        float v = base[(size_t)(l * CC + c) * 3 * CC + ((q & 1) ? CC : 0) + k] * scale;
        g_Bcath[t] = __float2half_rn(v);
    } else {
        int i = (b - FB - WB) * 256 + tid;
        int n = i / CC, c = i % CC;
        const float* xr = x + (size_t)n * 7;
        const float* wr = nW + (size_t)c * 7;
        float acc = nb[c];
#pragma unroll
        for (int k = 0; k < 7; k++) acc = fmaf(xr[k], wr[k], acc);
        g_h[i] = acc;
    }
}

// ---------------- CSR build (per-block int32/int64 self-detect) ----------------
__global__ void k_hist(const int* __restrict__ ei32) {
    int e = blockIdx.x * blockDim.x + threadIdx.x;
    int hi = (e < EE) ? ei32[2 * e + 1] : 0;
    int any32 = __syncthreads_or(hi != 0);
    if (e >= EE) return;
    int dst;
    if (any32) dst = ei32[EE + e];
    else       dst = (int)(((const long long*)ei32)[EE + e]);
    atomicAdd(&g_deg[dst], 1);
}

#define SC_NB 50
__global__ void __launch_bounds__(256) k_scan1() {
    __shared__ int sw[8];
    int b = blockIdx.x, tid = threadIdx.x, lane = tid & 31, wid = tid >> 5;
    int base = b * 1024 + tid * 4;
    int v[4];
    int run = 0;
#pragma unroll
    for (int i = 0; i < 4; i++) {
        int idx = base + i;
        int t = (idx <= NN) ? g_deg[idx] : 0;
        v[i] = run;
        run += t;
    }
    int incl = run;
#pragma unroll
    for (int d = 1; d < 32; d <<= 1) {
        int y = __shfl_up_sync(0xffffffffu, incl, d);
        if (lane >= d) incl += y;
    }
    if (lane == 31) sw[wid] = incl;
    __syncthreads();
    if (tid < 8) {
        int w = sw[tid];
        int wi = w;
#pragma unroll
        for (int d = 1; d < 8; d <<= 1) {
            int y = __shfl_up_sync(0xffu, wi, d);
            if (tid >= d) wi += y;
        }
        sw[tid] = wi - w;
        if (tid == 7) g_bsum[b] = wi;
    }
    __syncthreads();
    int off0 = sw[wid] + (incl - run);
#pragma unroll
    for (int i = 0; i < 4; i++) {
        int idx = base + i;
        if (idx <= NN) g_off[idx] = off0 + v[i];
    }
}

__global__ void __launch_bounds__(256) k_scan3() {
    __shared__ int wsum[2];
    int b = blockIdx.x, tid = threadIdx.x;
    if (tid < 64) {
        int v = (tid < b) ? g_bsum[tid] : 0;
#pragma unroll
        for (int d = 16; d; d >>= 1) v += __shfl_xor_sync(0xffffffffu, v, d);
        if ((tid & 31) == 0) wsum[tid >> 5] = v;
    }
    __syncthreads();
    int add = wsum[0] + wsum[1];
#pragma unroll
    for (int i = 0; i < 4; i++) {
        int idx = b * 1024 + tid * 4 + i;
        if (idx <= NN) {
            int o = g_off[idx] + add;
            g_off[idx] = o;
            if (idx < NN) g_cur[idx] = o;
        }
    }
}

__global__ void k_scatter(const int* __restrict__ ei32, const float* __restrict__ ea) {
    int e = blockIdx.x * blockDim.x + threadIdx.x;
    int hi = (e < EE) ? ei32[2 * e + 1] : 0;
    int any32 = __syncthreads_or(hi != 0);
    if (e >= EE) return;
    int src, dst;
    if (any32) {
        src = ei32[e];
        dst = ei32[EE + e];
    } else {
        const long long* ll = (const long long*)ei32;
        src = (int)ll[e];
        dst = (int)ll[EE + e];
    }
    int pos = atomicAdd(&g_cur[dst], 1);
    const float* a = ea + (size_t)e * 6;
    half2 x01 = __floats2half2_rn(a[0], a[1]);
    half2 x23 = __floats2half2_rn(a[2], a[3]);
    half2 x45 = __floats2half2_rn(a[4], a[5]);
    uint4 u;
    u.x = (uint32_t)src;
    u.y = *(uint32_t*)&x01;
    u.z = *(uint32_t*)&x23;
    u.w = *(uint32_t*)&x45;
    g_edge[pos] = u;
}

// ---------------- fp16 mma GEMM: T = h @ Bcath^T (M=NN, N=512, K=128) ----------------
#define LDH2 68
#define SMEM_MMA (3 * 128 * LDH2 * 4)

__device__ __forceinline__ void issue_b(const __half* __restrict__ Bsrc, uint32_t* sBuf, int tid) {
#pragma unroll
    for (int i = 0; i < 4; i++) {
        int idx = tid + i * 512;
        int row = idx >> 4, c8 = (idx & 15) << 3;
        uint32_t sa = (uint32_t)__cvta_generic_to_shared((const char*)(sBuf + row * LDH2) + c8 * 2);
        asm volatile("cp.async.ca.shared.global [%0], [%1], 16;"
                     :: "r"(sa), "l"(Bsrc + (size_t)row * CC + c8));
    }
    CP_COMMIT();
}

__device__ __forceinline__ void mma_compute(const uint32_t* sA, const uint32_t* sB,
                                            float acc[2][4][4],
                                            int wm, int wn, int gr, int tg) {
#pragma unroll
    for (int mi = 0; mi < 2; mi++)
#pragma unroll
        for (int ni = 0; ni < 4; ni++)
#pragma unroll
            for (int p = 0; p < 4; p++) acc[mi][ni][p] = 0.f;
#pragma unroll
    for (int ks = 0; ks < 8; ks++) {
        const int k0 = ks * 8;
        uint32_t a[2][4];
#pragma unroll
        for (int mi = 0; mi < 2; mi++) {
            const uint32_t* ap = sA + (wm + mi * 16 + gr) * LDH2 + k0 + tg;
            a[mi][0] = ap[0];
            a[mi][1] = ap[8 * LDH2];
            a[mi][2] = ap[4];
            a[mi][3] = ap[8 * LDH2 + 4];
        }
        uint32_t b[4][2];
#pragma unroll
        for (int ni = 0; ni < 4; ni++) {
            const uint32_t* bp = sB + (wn + ni * 8 + gr) * LDH2 + k0 + tg;
            b[ni][0] = bp[0];
            b[ni][1] = bp[4];
        }
#pragma unroll
        for (int mi = 0; mi < 2; mi++)
#pragma unroll
            for (int ni = 0; ni < 4; ni++)
                mma_f16(acc[mi][ni], a[mi], b[ni]);
    }
}

// q: 0=hf_i 1=hf_j 2=hs_i 3=hs_j ; Ti/Tj interleaved [hf x4 | hs x4] per 4-col group
__device__ __forceinline__ void mma_epi(float acc[2][4][4], int q,
                                        int bm, int wm, int wn, int gr, int tg) {
    __half* buf = (q & 1) ? g_Tj : g_Ti;
    const int add = (q >> 1) ? 4 : 0;
#pragma unroll
    for (int mi = 0; mi < 2; mi++) {
        int r0 = bm + wm + mi * 16 + gr;
        int r1 = r0 + 8;
#pragma unroll
        for (int ni = 0; ni < 4; ni++) {
            int lc = wn + ni * 8 + tg * 2;
            int i0 = ((lc >> 2) << 3) + (lc & 3) + add;
            if (r0 < NN) *(__half2*)(buf + (size_t)r0 * 256 + i0) = __floats2half2_rn(acc[mi][ni][0], acc[mi][ni][1]);
            if (r1 < NN) *(__half2*)(buf + (size_t)r1 * 256 + i0) = __floats2half2_rn(acc[mi][ni][2], acc[mi][ni][3]);
        }
    }
}

__global__ void __launch_bounds__(512) k_mma(int l) {
    extern __shared__ uint32_t smem_u[];
    uint32_t* sA = smem_u;
    uint32_t* sB0 = smem_u + 128 * LDH2;
    uint32_t* sB1 = smem_u + 2 * 128 * LDH2;
    const int tid = threadIdx.x;
    const int wid = tid >> 5, lane = tid & 31;
    const int bm = blockIdx.x * 128;
    const int wm = (wid >> 2) * 32, wn = (wid & 3) * 32;
    const int gr = lane >> 2, tg = lane & 3;

    const __half* Bl = g_Bcath + (size_t)l * 512 * CC;
    issue_b(Bl + 0 * 128 * CC, sB0, tid);
    issue_b(Bl + 1 * 128 * CC, sB1, tid);

#pragma unroll
    for (int i = 0; i < 8; i++) {
        int idx = tid + i * 512;
        int row = idx >> 5;
        int col2 = (idx & 31) << 1;
        float4 v = make_float4(0.f, 0.f, 0.f, 0.f);
        if (bm + row < NN) v = *(const float4*)(g_h + (size_t)(bm + row) * CC + (col2 << 1));
        half2 h0 = __floats2half2_rn(v.x, v.y);
        half2 h1 = __floats2half2_rn(v.z, v.w);
        uint2 pk = make_uint2(*(uint32_t*)&h0, *(uint32_t*)&h1);
        *(uint2*)(sA + row * LDH2 + col2) = pk;
    }

    float acc[2][4][4];

    CP_WAIT1(); __syncthreads();
    mma_compute(sA, sB0, acc, wm, wn, gr, tg);
    mma_epi(acc, 0, bm, wm, wn, gr, tg);
    __syncthreads();
    issue_b(Bl + 2 * 128 * CC, sB0, tid);
    CP_WAIT1(); __syncthreads();
    mma_compute(sA, sB1, acc, wm, wn, gr, tg);
    mma_epi(acc, 1, bm, wm, wn, gr, tg);
    __syncthreads();
    issue_b(Bl + 3 * 128 * CC, sB1, tid);
    CP_WAIT1(); __syncthreads();
    mma_compute(sA, sB0, acc, wm, wn, gr, tg);
    mma_epi(acc, 2, bm, wm, wn, gr, tg);
    __syncthreads();
    CP_WAIT0(); __syncthreads();
    mma_compute(sA, sB1, acc, wm, wn, gr, tg);
    mma_epi(acc, 3, bm, wm, wn, gr, tg);
}

// ---------------- edge message (shared by both ILP streams) ----------------
__device__ __forceinline__ void edge_msg(uint4 ec, uint4 tj, int lane,
                                         const half2* sAfa, const half2* sAfb,
                                         const half2* sAsa, const half2* sAsb,
                                         half2 fi2a, half2 fi2b, float4 si,
                                         half2& m0, half2& m1) {
    half2 p01 = *(half2*)&ec.y;
    half2 p23 = *(half2*)&ec.z;
    half2 p45 = *(half2*)&ec.w;
    half2 a0 = __low2half2(p01), a1 = __high2half2(p01);
    half2 a2 = __low2half2(p23), a3 = __high2half2(p23);
    half2 a4 = __low2half2(p45), a5 = __high2half2(p45);

    half2 fa = __hmul2(a0, sAfa[lane]);
    half2 fb = __hmul2(a0, sAfb[lane]);
    half2 sa = __hmul2(a0, sAsa[lane]);
    half2 sb = __hmul2(a0, sAsb[lane]);
    fa = __hfma2(a1, sAfa[32 + lane], fa);  fb = __hfma2(a1, sAfb[32 + lane], fb);
    sa = __hfma2(a1, sAsa[32 + lane], sa);  sb = __hfma2(a1, sAsb[32 + lane], sb);
    fa = __hfma2(a2, sAfa[64 + lane], fa);  fb = __hfma2(a2, sAfb[64 + lane], fb);
    sa = __hfma2(a2, sAsa[64 + lane], sa);  sb = __hfma2(a2, sAsb[64 + lane], sb);
    fa = __hfma2(a3, sAfa[96 + lane], fa);  fb = __hfma2(a3, sAfb[96 + lane], fb);
    sa = __hfma2(a3, sAsa[96 + lane], sa);  sb = __hfma2(a3, sAsb[96 + lane], sb);
    fa = __hfma2(a4, sAfa[128 + lane], fa); fb = __hfma2(a4, sAfb[128 + lane], fb);
    sa = __hfma2(a4, sAsa[128 + lane], sa); sb = __hfma2(a4, sAsb[128 + lane], sb);
    fa = __hfma2(a5, sAfa[160 + lane], fa); fb = __hfma2(a5, sAfb[160 + lane], fb);
    sa = __hfma2(a5, sAsa[160 + lane], sa); sb = __hfma2(a5, sAsb[160 + lane], sb);

    fa = __hadd2(fa, *(half2*)&tj.x);
    fb = __hadd2(fb, *(half2*)&tj.y);
    sa = __hadd2(sa, *(half2*)&tj.z);
    sb = __hadd2(sb, *(half2*)&tj.w);

    half2 t0 = h2tanh_(__hadd2(fa, fi2a));
    half2 t1 = h2tanh_(__hadd2(fb, fi2b));

    float2 s01 = __half22float2(sa);
    float2 s23 = __half22float2(sb);
    float u0 = ex2f(si.x + s01.x);
    float u1 = ex2f(si.y + s01.y);
    float u2 = ex2f(si.z + s23.x);
    float u3 = ex2f(si.w + s23.y);
    half2 sp01 = __floats2half2_rn(lg2f(1.f + u0), lg2f(1.f + u1));
    half2 sp23 = __floats2half2_rn(lg2f(1.f + u2), lg2f(1.f + u3));

    m0 = __hfma2(t0, sp01, sp01);
    m1 = __hfma2(t1, sp23, sp23);
}

// ---------------- per-layer aggregation + BN + residual (+ fused head on last) ----------------
__global__ void __launch_bounds__(256) k_agg(const float* __restrict__ gamma,
                                             const float* __restrict__ beta,
                                             const float* __restrict__ bmean,
                                             const float* __restrict__ bvar,
                                             int l, int last,
                                             const float* __restrict__ linW,
                                             const float* __restrict__ linb,
                                             float* __restrict__ out) {
    __shared__ half2 sAfa[192], sAfb[192], sAsa[192], sAsb[192];
    __shared__ float4 sC[64];
    int tid = threadIdx.x;
    if (tid < 192) {
        int k = tid >> 5, ln = tid & 31;
        const float* Af = g_AfT + (size_t)l * 6 * CC + k * CC + 4 * ln;
        const float* As_ = g_AsT + (size_t)l * 6 * CC + k * CC + 4 * ln;
        sAfa[tid] = __floats2half2_rn(Af[0], Af[1]);
        sAfb[tid] = __floats2half2_rn(Af[2], Af[3]);
        sAsa[tid] = __floats2half2_rn(As_[0], As_[1]);
        sAsb[tid] = __floats2half2_rn(As_[2], As_[3]);
    }
    if (tid < 32)
        sC[tid] = ((const float4*)(g_cf + (size_t)l * CC))[tid];
    else if (tid < 64)
        sC[tid] = ((const float4*)(g_cs + (size_t)l * CC))[tid - 32];
    __syncthreads();

    int lane = tid & 31;
    int n = (blockIdx.x * 256 + tid) >> 5;
    if (n >= NN) return;

    uint4 ti = ((const uint4*)g_Ti)[(size_t)n * 32 + lane];
    float4 c0 = sC[lane], c1 = sC[32 + lane];
    half2 fi2a = __hadd2(*(half2*)&ti.x, __floats2half2_rn(c0.x, c0.y));
    half2 fi2b = __hadd2(*(half2*)&ti.y, __floats2half2_rn(c0.z, c0.w));
    float2 sia = __half22float2(*(half2*)&ti.z);
    float2 sib = __half22float2(*(half2*)&ti.w);
    float4 si = make_float4(sia.x + c1.x, sia.y + c1.y, sib.x + c1.z, sib.y + c1.w);

    const uint4* Tj4 = (const uint4*)g_Tj;

    half2 mx0 = __float2half2_rn(0.f);
    half2 mx1 = mx0;
    int beg = g_off[n], end = g_off[n + 1];

    // 2-edge ILP with pair-ahead prefetch
    uint4 eA, eB, tA, tB;
    int j = beg;
    if (j < end) {
        eA = g_edge[j];
        tA = Tj4[(size_t)eA.x * 32 + lane];
    }
    if (j + 1 < end) {
        eB = g_edge[j + 1];
        tB = Tj4[(size_t)eB.x * 32 + lane];
    }

    while (j + 1 < end) {
        uint4 ceA = eA, ctA = tA, ceB = eB, ctB = tB;
        j += 2;
        if (j < end) {
            eA = g_edge[j];
            tA = Tj4[(size_t)eA.x * 32 + lane];
        }
        if (j + 1 < end) {
            eB = g_edge[j + 1];
            tB = Tj4[(size_t)eB.x * 32 + lane];
        }
        half2 mA0, mA1, mB0, mB1;
        edge_msg(ceA, ctA, lane, sAfa, sAfb, sAsa, sAsb, fi2a, fi2b, si, mA0, mA1);
        edge_msg(ceB, ctB, lane, sAfa, sAfb, sAsa, sAsb, fi2a, fi2b, si, mB0, mB1);
        mx0 = __hmax2(mx0, __hmax2(mA0, mB0));
        mx1 = __hmax2(mx1, __hmax2(mA1, mB1));
    }
    if (j < end) {
        half2 mA0, mA1;
        edge_msg(eA, tA, lane, sAfa, sAfb, sAsa, sAsb, fi2a, fi2b, si, mA0, mA1);
        mx0 = __hmax2(mx0, mA0);
        mx1 = __hmax2(mx1, mA1);
    }

    float2 mf0 = __half22float2(mx0);
    float2 mf1 = __half22float2(mx1);

    float4 g4 = ((const float4*)(gamma + (size_t)l * CC))[lane];
    float4 b4 = ((const float4*)(beta + (size_t)l * CC))[lane];
    float4 m4 = ((const float4*)(bmean + (size_t)l * CC))[lane];
    float4 v4 = ((const float4*)(bvar + (size_t)l * CC))[lane];
    float4* H4 = (float4*)g_h;
    float4 h4 = H4[(size_t)n * 32 + lane];
    h4.x += (mf0.x * MSCALE - m4.x) * rsqrtf(v4.x + 1e-5f) * g4.x + b4.x;
    h4.y += (mf0.y * MSCALE - m4.y) * rsqrtf(v4.y + 1e-5f) * g4.y + b4.y;
    h4.z += (mf1.x * MSCALE - m4.z) * rsqrtf(v4.z + 1e-5f) * g4.z + b4.z;
    h4.w += (mf1.y * MSCALE - m4.w) * rsqrtf(v4.w + 1e-5f) * g4.w + b4.w;

    if (!last) {
        H4[(size_t)n * 32 + lane] = h4;
    } else {
        ((float4*)(out + (size_t)NN * KK))[(size_t)n * 32 + lane] = h4;
#pragma unroll
        for (int jq = 0; jq < KK; jq++) {
            float4 w = ((const float4*)linW)[jq * 32 + lane];
            float p = h4.x * w.x + h4.y * w.y + h4.z * w.z + h4.w * w.w;
#pragma unroll
            for (int d = 16; d; d >>= 1) p += __shfl_xor_sync(0xffffffffu, p, d);
            if (lane == 0) out[(size_t)n * KK + jq] = p + __ldg(linb + jq);
        }
    }
}

// ---------------- launch ----------------
extern "C" void kernel_launch(void* const* d_in, const int* in_sizes, int n_in,
                              void* d_out, int out_size) {
    const float* x       = (const float*)d_in[0];
    const int*   ei      = (const int*)d_in[1];
    const float* ea      = (const float*)d_in[2];
    const float* node_W  = (const float*)d_in[3];
    const float* node_b  = (const float*)d_in[4];
    const float* edge_W  = (const float*)d_in[5];
    const float* edge_b  = (const float*)d_in[6];
    const float* Wf      = (const float*)d_in[7];
    const float* bf      = (const float*)d_in[8];
    const float* Ws      = (const float*)d_in[9];
    const float* bs      = (const float*)d_in[10];
    const float* gamma   = (const float*)d_in[11];
    const float* beta    = (const float*)d_in[12];
    const float* bn_mean = (const float*)d_in[13];
    const float* bn_var  = (const float*)d_in[14];
    const float* lin_W   = (const float*)d_in[15];
    const float* lin_b   = (const float*)d_in[16];
    float* out = (float*)d_out;

    cudaFuncSetAttribute(k_mma, cudaFuncAttributeMaxDynamicSharedMemorySize, SMEM_MMA);

    cudaStream_t s2;
    cudaStreamCreateWithFlags(&s2, cudaStreamNonBlocking);
    cudaEvent_t evFork, evCSR;
    cudaEventCreateWithFlags(&evFork, cudaEventDisableTiming);
    cudaEventCreateWithFlags(&evCSR, cudaEventDisableTiming);

    int mgrid = (NN + 127) / 128;
    int agrid = (NN * 32 + 255) / 256;

    cudaEventRecord(evFork, 0);
    cudaStreamWaitEvent(s2, evFork, 0);

    k_zero<<<196, 256, 0, s2>>>();                                   // 0
    k_hist<<<(EE + 255) / 256, 256, 0, s2>>>(ei);                    // 1
    k_setup<<<FB + WB + NB, 256>>>(x, node_W, node_b, Wf, bf, Ws, bs,
                                   edge_W, edge_b);                  // 2
    k_mma<<<mgrid, 512, SMEM_MMA>>>(0);                              // 3 (profiled)
    k_scan1<<<SC_NB, 256, 0, s2>>>();                                // 4
    k_scan3<<<SC_NB, 256, 0, s2>>>();                                // 5
    k_scatter<<<(EE + 255) / 256, 256, 0, s2>>>(ei, ea);             // 6
    cudaEventRecord(evCSR, s2);

    cudaStreamWaitEvent(0, evCSR, 0);
    k_agg<<<agrid, 256>>>(gamma, beta, bn_mean, bn_var, 0, 0, lin_W, lin_b, out);

    k_mma<<<mgrid, 512, SMEM_MMA>>>(1);
    k_agg<<<agrid, 256>>>(gamma, beta, bn_mean, bn_var, 1, 0, lin_W, lin_b, out);
    k_mma<<<mgrid, 512, SMEM_MMA>>>(2);
    k_agg<<<agrid, 256>>>(gamma, beta, bn_mean, bn_var, 2, 1, lin_W, lin_b, out);
}

// round 13
// speedup vs baseline: 1.0632x; 1.0632x over previous
#include <cuda_runtime.h>
#include <cuda_fp16.h>
#include <cstdint>

#define NN 50000
#define EE 800000
#define CC 128
#define LL 3
#define KK 10

#define LOG2E 1.4426950408889634f
#define MSCALE 0.34657359027997264f  // 0.5 * ln2

// ---------------- scratch ----------------
__device__ __align__(16) float  g_h[NN * CC];
__device__ __align__(16) __half g_Ti[(size_t)NN * 256];       // interleaved [hf_i x4 | hs_i x4]
__device__ __align__(16) __half g_Tj[(size_t)NN * 256];       // interleaved [hf_j x4 | hs_j x4]
__device__ __align__(16) __half g_Bcath[LL * 512 * CC];       // prescaled half weight rows
__device__ __align__(16) float  g_AfT[LL * 6 * CC];           // x0.5
__device__ __align__(16) float  g_AsT[LL * 6 * CC];           // xlog2e
__device__ __align__(16) float  g_cf[LL * CC];
__device__ __align__(16) float  g_cs[LL * CC];
__device__ int   g_deg[NN + 1];                               // zero-init; scan1 re-zeros
__device__ int   g_off[NN + 1];
__device__ int   g_cur[NN];
__device__ __align__(16) uint4 g_edge[EE];  // {src, ea01, ea23, ea45}
__device__ int   g_bsum[64];

// ---------------- math helpers ----------------
__device__ __forceinline__ float ex2f(float x) {
    float r; asm("ex2.approx.f32 %0, %1;" : "=f"(r) : "f"(x)); return r;
}
__device__ __forceinline__ float lg2f(float x) {
    float r; asm("lg2.approx.f32 %0, %1;" : "=f"(r) : "f"(x)); return r;
}
__device__ __forceinline__ half2 h2tanh_(half2 x) {
    uint32_t xi = *(uint32_t*)&x, ri;
    asm("tanh.approx.f16x2 %0, %1;" : "=r"(ri) : "r"(xi));
    return *(half2*)&ri;
}
__device__ __forceinline__ void mma_f16(float* d, const uint32_t* a, const uint32_t* b) {
    asm volatile(
        "mma.sync.aligned.m16n8k16.row.col.f32.f16.f16.f32 "
        "{%0,%1,%2,%3}, {%4,%5,%6,%7}, {%8,%9}, {%0,%1,%2,%3};"
        : "+f"(d[0]), "+f"(d[1]), "+f"(d[2]), "+f"(d[3])
        : "r"(a[0]), "r"(a[1]), "r"(a[2]), "r"(a[3]), "r"(b[0]), "r"(b[1]));
}
__device__ __forceinline__ void ldsm_x4(uint32_t& r0, uint32_t& r1, uint32_t& r2, uint32_t& r3,
                                        uint32_t saddr) {
    asm volatile("ldmatrix.sync.aligned.m8n8.x4.shared.b16 {%0,%1,%2,%3}, [%4];"
                 : "=r"(r0), "=r"(r1), "=r"(r2), "=r"(r3) : "r"(saddr));
}
__device__ __forceinline__ void ldsm_x2(uint32_t& r0, uint32_t& r1, uint32_t saddr) {
    asm volatile("ldmatrix.sync.aligned.m8n8.x2.shared.b16 {%0,%1}, [%2];"
                 : "=r"(r0), "=r"(r1) : "r"(saddr));
}
#define CP_COMMIT() asm volatile("cp.async.commit_group;")
#define CP_WAIT1()  asm volatile("cp.async.wait_group 1;")
#define CP_WAIT0()  asm volatile("cp.async.wait_group 0;")

// ---------------- fused setup: fold | bprep(half) | node_encode ----------------
#define FB 21
#define WB 768
#define NB 25000
__global__ void k_setup(const float* __restrict__ x, const float* __restrict__ nW,
                        const float* __restrict__ nb,
                        const float* __restrict__ Wf, const float* __restrict__ bf,
                        const float* __restrict__ Ws, const float* __restrict__ bs,
                        const float* __restrict__ eW, const float* __restrict__ eb) {
    int b = blockIdx.x, tid = threadIdx.x;
    if (b < FB) {
        int t = b * 256 + tid;
        if (t >= LL * CC * 14) return;
        int l = t / (CC * 14);
        int r = t % (CC * 14);
        int c = r / 14, kk = r % 14;
        const float* rf = Wf + ((size_t)(l * CC + c) * 3 * CC) + 2 * CC;
        const float* rs = Ws + ((size_t)(l * CC + c) * 3 * CC) + 2 * CC;
        if (kk < 6) {
            float s = 0.f;
            for (int j = 0; j < CC; j++) s = fmaf(rf[j], eW[j * 6 + kk], s);
            g_AfT[l * 6 * CC + kk * CC + c] = s * 0.5f;
        } else if (kk < 12) {
            int k = kk - 6;
            float s = 0.f;
            for (int j = 0; j < CC; j++) s = fmaf(rs[j], eW[j * 6 + k], s);
            g_AsT[l * 6 * CC + k * CC + c] = s * LOG2E;
        } else if (kk == 12) {
            float s = bf[l * CC + c];
            for (int j = 0; j < CC; j++) s = fmaf(rf[j], eb[j], s);
            g_cf[l * CC + c] = s * 0.5f;
        } else {
            float s = bs[l * CC + c];
            for (int j = 0; j < CC; j++) s = fmaf(rs[j], eb[j], s);
            g_cs[l * CC + c] = s * LOG2E;
        }
    } else if (b < FB + WB) {
        int t = (b - FB) * 256 + tid;
        int l = t / (512 * CC);
        int r = t % (512 * CC);
        int n = r / CC, k = r % CC;
        int q = n >> 7, c = n & 127;
        const float* base = (q < 2 ? Wf : Ws);
        float scale = (q < 2) ? 0.5f : LOG2E;
        float v = base[(size_t)(l * CC + c) * 3 * CC + ((q & 1) ? CC : 0) + k] * scale;
        g_Bcath[t] = __float2half_rn(v);
    } else {
        int i = (b - FB - WB) * 256 + tid;
        int n = i / CC, c = i % CC;
        const float* xr = x + (size_t)n * 7;
        const float* wr = nW + (size_t)c * 7;
        float acc = nb[c];
#pragma unroll
        for (int k = 0; k < 7; k++) acc = fmaf(xr[k], wr[k], acc);
        g_h[i] = acc;
    }
}

// ---------------- CSR build (per-block int32/int64 self-detect) ----------------
__global__ void k_hist(const int* __restrict__ ei32) {
    int e = blockIdx.x * blockDim.x + threadIdx.x;
    int hi = (e < EE) ? ei32[2 * e + 1] : 0;
    int any32 = __syncthreads_or(hi != 0);
    if (e >= EE) return;
    int dst;
    if (any32) dst = ei32[EE + e];
    else       dst = (int)(((const long long*)ei32)[EE + e]);
    atomicAdd(&g_deg[dst], 1);
}

#define SC_NB 50
__global__ void __launch_bounds__(256) k_scan1() {
    __shared__ int sw[8];
    int b = blockIdx.x, tid = threadIdx.x, lane = tid & 31, wid = tid >> 5;
    int base = b * 1024 + tid * 4;
    int v[4];
    int run = 0;
#pragma unroll
    for (int i = 0; i < 4; i++) {
        int idx = base + i;
        int t = 0;
        if (idx <= NN) {
            t = g_deg[idx];
            g_deg[idx] = 0;   // reset for the next graph replay
        }
        v[i] = run;
        run += t;
    }
    int incl = run;
#pragma unroll
    for (int d = 1; d < 32; d <<= 1) {
        int y = __shfl_up_sync(0xffffffffu, incl, d);
        if (lane >= d) incl += y;
    }
    if (lane == 31) sw[wid] = incl;
    __syncthreads();
    if (tid < 8) {
        int w = sw[tid];
        int wi = w;
#pragma unroll
        for (int d = 1; d < 8; d <<= 1) {
            int y = __shfl_up_sync(0xffu, wi, d);
            if (tid >= d) wi += y;
        }
        sw[tid] = wi - w;
        if (tid == 7) g_bsum[b] = wi;
    }
    __syncthreads();
    int off0 = sw[wid] + (incl - run);
#pragma unroll
    for (int i = 0; i < 4; i++) {
        int idx = base + i;
        if (idx <= NN) g_off[idx] = off0 + v[i];
    }
}

__global__ void __launch_bounds__(256) k_scan3() {
    __shared__ int wsum[2];
    int b = blockIdx.x, tid = threadIdx.x;
    if (tid < 64) {
        int v = (tid < b) ? g_bsum[tid] : 0;
#pragma unroll
        for (int d = 16; d; d >>= 1) v += __shfl_xor_sync(0xffffffffu, v, d);
        if ((tid & 31) == 0) wsum[tid >> 5] = v;
    }
    __syncthreads();
    int add = wsum[0] + wsum[1];
#pragma unroll
    for (int i = 0; i < 4; i++) {
        int idx = b * 1024 + tid * 4 + i;
        if (idx <= NN) {
            int o = g_off[idx] + add;
            g_off[idx] = o;
            if (idx < NN) g_cur[idx] = o;
        }
    }
}

__global__ void k_scatter(const int* __restrict__ ei32, const float* __restrict__ ea) {
    int e = blockIdx.x * blockDim.x + threadIdx.x;
    int hi = (e < EE) ? ei32[2 * e + 1] : 0;
    int any32 = __syncthreads_or(hi != 0);
    if (e >= EE) return;
    int src, dst;
    if (any32) {
        src = ei32[e];
        dst = ei32[EE + e];
    } else {
        const long long* ll = (const long long*)ei32;
        src = (int)ll[e];
        dst = (int)ll[EE + e];
    }
    int pos = atomicAdd(&g_cur[dst], 1);
    const float* a = ea + (size_t)e * 6;
    half2 x01 = __floats2half2_rn(a[0], a[1]);
    half2 x23 = __floats2half2_rn(a[2], a[3]);
    half2 x45 = __floats2half2_rn(a[4], a[5]);
    uint4 u;
    u.x = (uint32_t)src;
    u.y = *(uint32_t*)&x01;
    u.z = *(uint32_t*)&x23;
    u.w = *(uint32_t*)&x45;
    g_edge[pos] = u;
}

// ---------------- fp16 mma GEMM: T = h @ Bcath^T (M=NN, N=512, K=128) ----------------
// 512 threads: 16 warps, 4x4 warp grid of 32x32 tiles, m16n8k16, ldmatrix fragments.
#define LDH2 68
#define SMEM_MMA (3 * 128 * LDH2 * 4)

__device__ __forceinline__ void issue_b(const __half* __restrict__ Bsrc, uint32_t* sBuf, int tid) {
#pragma unroll
    for (int i = 0; i < 4; i++) {
        int idx = tid + i * 512;
        int row = idx >> 4, c8 = (idx & 15) << 3;
        uint32_t sa = (uint32_t)__cvta_generic_to_shared((const char*)(sBuf + row * LDH2) + c8 * 2);
        asm volatile("cp.async.ca.shared.global [%0], [%1], 16;"
                     :: "r"(sa), "l"(Bsrc + (size_t)row * CC + c8));
    }
    CP_COMMIT();
}

// aBase/bBase: smem byte addresses of the A / B tiles
__device__ __forceinline__ void mma_compute(uint32_t aBase, uint32_t bBase,
                                            float acc[2][4][4],
                                            int wm, int wn, int lane) {
#pragma unroll
    for (int mi = 0; mi < 2; mi++)
#pragma unroll
        for (int ni = 0; ni < 4; ni++)
#pragma unroll
            for (int p = 0; p < 4; p++) acc[mi][ni][p] = 0.f;

    uint32_t aAddr[2], bAddr[4];
#pragma unroll
    for (int mi = 0; mi < 2; mi++)
        aAddr[mi] = aBase + (((wm + mi * 16 + (lane & 15)) * LDH2 + ((lane >> 4) << 2)) << 2);
#pragma unroll
    for (int ni = 0; ni < 4; ni++)
        bAddr[ni] = bBase + (((wn + ni * 8 + (lane & 7)) * LDH2 + (((lane >> 3) & 1) << 2)) << 2);

#pragma unroll
    for (int ks = 0; ks < 8; ks++) {
        uint32_t a[2][4];
#pragma unroll
        for (int mi = 0; mi < 2; mi++) {
            ldsm_x4(a[mi][0], a[mi][1], a[mi][2], a[mi][3], aAddr[mi]);
            aAddr[mi] += 32;
        }
        uint32_t b[4][2];
#pragma unroll
        for (int ni = 0; ni < 4; ni++) {
            ldsm_x2(b[ni][0], b[ni][1], bAddr[ni]);
            bAddr[ni] += 32;
        }
#pragma unroll
        for (int mi = 0; mi < 2; mi++)
#pragma unroll
            for (int ni = 0; ni < 4; ni++)
                mma_f16(acc[mi][ni], a[mi], b[ni]);
    }
}

// q: 0=hf_i 1=hf_j 2=hs_i 3=hs_j ; Ti/Tj interleaved [hf x4 | hs x4] per 4-col group
__device__ __forceinline__ void mma_epi(float acc[2][4][4], int q,
                                        int bm, int wm, int wn, int gr, int tg) {
    __half* buf = (q & 1) ? g_Tj : g_Ti;
    const int add = (q >> 1) ? 4 : 0;
#pragma unroll
    for (int mi = 0; mi < 2; mi++) {
        int r0 = bm + wm + mi * 16 + gr;
        int r1 = r0 + 8;
#pragma unroll
        for (int ni = 0; ni < 4; ni++) {
            int lc = wn + ni * 8 + tg * 2;
            int i0 = ((lc >> 2) << 3) + (lc & 3) + add;
            if (r0 < NN) *(__half2*)(buf + (size_t)r0 * 256 + i0) = __floats2half2_rn(acc[mi][ni][0], acc[mi][ni][1]);
            if (r1 < NN) *(__half2*)(buf + (size_t)r1 * 256 + i0) = __floats2half2_rn(acc[mi][ni][2], acc[mi][ni][3]);
        }
    }
}

__global__ void __launch_bounds__(512) k_mma(int l) {
    extern __shared__ uint32_t smem_u[];
    uint32_t* sA = smem_u;
    const int tid = threadIdx.x;
    const int wid = tid >> 5, lane = tid & 31;
    const int bm = blockIdx.x * 128;
    const int wm = (wid >> 2) * 32, wn = (wid & 3) * 32;
    const int gr = lane >> 2, tg = lane & 3;

    uint32_t sbase = (uint32_t)__cvta_generic_to_shared(smem_u);
    uint32_t aBase = sbase;
    uint32_t b0Base = sbase + 128 * LDH2 * 4;
    uint32_t b1Base = sbase + 2 * 128 * LDH2 * 4;
    uint32_t* sB0 = smem_u + 128 * LDH2;
    uint32_t* sB1 = smem_u + 2 * 128 * LDH2;

    const __half* Bl = g_Bcath + (size_t)l * 512 * CC;
    issue_b(Bl + 0 * 128 * CC, sB0, tid);
    issue_b(Bl + 1 * 128 * CC, sB1, tid);

    // A load + f16 convert (once)
#pragma unroll
    for (int i = 0; i < 8; i++) {
        int idx = tid + i * 512;
        int row = idx >> 5;
        int col2 = (idx & 31) << 1;
        float4 v = make_float4(0.f, 0.f, 0.f, 0.f);
        if (bm + row < NN) v = *(const float4*)(g_h + (size_t)(bm + row) * CC + (col2 << 1));
        half2 h0 = __floats2half2_rn(v.x, v.y);
        half2 h1 = __floats2half2_rn(v.z, v.w);
        uint2 pk = make_uint2(*(uint32_t*)&h0, *(uint32_t*)&h1);
        *(uint2*)(sA + row * LDH2 + col2) = pk;
    }

    float acc[2][4][4];

    CP_WAIT1(); __syncthreads();
    mma_compute(aBase, b0Base, acc, wm, wn, lane);
    mma_epi(acc, 0, bm, wm, wn, gr, tg);
    __syncthreads();
    issue_b(Bl + 2 * 128 * CC, sB0, tid);
    CP_WAIT1(); __syncthreads();
    mma_compute(aBase, b1Base, acc, wm, wn, lane);
    mma_epi(acc, 1, bm, wm, wn, gr, tg);
    __syncthreads();
    issue_b(Bl + 3 * 128 * CC, sB1, tid);
    CP_WAIT1(); __syncthreads();
    mma_compute(aBase, b0Base, acc, wm, wn, lane);
    mma_epi(acc, 2, bm, wm, wn, gr, tg);
    __syncthreads();
    CP_WAIT0(); __syncthreads();
    mma_compute(aBase, b1Base, acc, wm, wn, lane);
    mma_epi(acc, 3, bm, wm, wn, gr, tg);
}

// ---------------- per-layer aggregation + BN + residual (+ fused head on last) ----------------
__global__ void __launch_bounds__(256) k_agg(const float* __restrict__ gamma,
                                             const float* __restrict__ beta,
                                             const float* __restrict__ bmean,
                                             const float* __restrict__ bvar,
                                             int l, int last,
                                             const float* __restrict__ linW,
                                             const float* __restrict__ linb,
                                             float* __restrict__ out) {
    __shared__ half2 sAfa[192], sAfb[192], sAsa[192], sAsb[192];
    __shared__ float4 sC[64];
    int tid = threadIdx.x;
    if (tid < 192) {
        int k = tid >> 5, ln = tid & 31;
        const float* Af = g_AfT + (size_t)l * 6 * CC + k * CC + 4 * ln;
        const float* As_ = g_AsT + (size_t)l * 6 * CC + k * CC + 4 * ln;
        sAfa[tid] = __floats2half2_rn(Af[0], Af[1]);
        sAfb[tid] = __floats2half2_rn(Af[2], Af[3]);
        sAsa[tid] = __floats2half2_rn(As_[0], As_[1]);
        sAsb[tid] = __floats2half2_rn(As_[2], As_[3]);
    }
    if (tid < 32)
        sC[tid] = ((const float4*)(g_cf + (size_t)l * CC))[tid];
    else if (tid < 64)
        sC[tid] = ((const float4*)(g_cs + (size_t)l * CC))[tid - 32];
    __syncthreads();

    int lane = tid & 31;
    int n = (blockIdx.x * 256 + tid) >> 5;
    if (n >= NN) return;

    uint4 ti = ((const uint4*)g_Ti)[(size_t)n * 32 + lane];
    float4 c0 = sC[lane], c1 = sC[32 + lane];
    half2 fi2a = __hadd2(*(half2*)&ti.x, __floats2half2_rn(c0.x, c0.y));
    half2 fi2b = __hadd2(*(half2*)&ti.y, __floats2half2_rn(c0.z, c0.w));
    float2 sia = __half22float2(*(half2*)&ti.z);
    float2 sib = __half22float2(*(half2*)&ti.w);
    float4 si = make_float4(sia.x + c1.x, sia.y + c1.y, sib.x + c1.z, sib.y + c1.w);

    const uint4* Tj4 = (const uint4*)g_Tj;

    half2 mx0 = __float2half2_rn(0.f);
    half2 mx1 = mx0;
    int beg = g_off[n], end = g_off[n + 1];

    uint4 e0, e1, tj0;
    if (beg < end) {
        e0 = g_edge[beg];
        tj0 = Tj4[(size_t)e0.x * 32 + lane];
    }
    if (beg + 1 < end) e1 = g_edge[beg + 1];

    for (int j = beg; j < end; j++) {
        uint4 ec = e0;
        uint4 tj = tj0;
        if (j + 1 < end) {
            tj0 = Tj4[(size_t)e1.x * 32 + lane];
            e0 = e1;
        }
        if (j + 2 < end) e1 = g_edge[j + 2];

        half2 p01 = *(half2*)&ec.y;
        half2 p23 = *(half2*)&ec.z;
        half2 p45 = *(half2*)&ec.w;
        half2 a0 = __low2half2(p01), a1 = __high2half2(p01);
        half2 a2 = __low2half2(p23), a3 = __high2half2(p23);
        half2 a4 = __low2half2(p45), a5 = __high2half2(p45);

        half2 fa = __hmul2(a0, sAfa[lane]);
        half2 fb = __hmul2(a0, sAfb[lane]);
        half2 sa = __hmul2(a0, sAsa[lane]);
        half2 sb = __hmul2(a0, sAsb[lane]);
        fa = __hfma2(a1, sAfa[32 + lane], fa);  fb = __hfma2(a1, sAfb[32 + lane], fb);
        sa = __hfma2(a1, sAsa[32 + lane], sa);  sb = __hfma2(a1, sAsb[32 + lane], sb);
        fa = __hfma2(a2, sAfa[64 + lane], fa);  fb = __hfma2(a2, sAfb[64 + lane], fb);
        sa = __hfma2(a2, sAsa[64 + lane], sa);  sb = __hfma2(a2, sAsb[64 + lane], sb);
        fa = __hfma2(a3, sAfa[96 + lane], fa);  fb = __hfma2(a3, sAfb[96 + lane], fb);
        sa = __hfma2(a3, sAsa[96 + lane], sa);  sb = __hfma2(a3, sAsb[96 + lane], sb);
        fa = __hfma2(a4, sAfa[128 + lane], fa); fb = __hfma2(a4, sAfb[128 + lane], fb);
        sa = __hfma2(a4, sAsa[128 + lane], sa); sb = __hfma2(a4, sAsb[128 + lane], sb);
        fa = __hfma2(a5, sAfa[160 + lane], fa); fb = __hfma2(a5, sAfb[160 + lane], fb);
        sa = __hfma2(a5, sAsa[160 + lane], sa); sb = __hfma2(a5, sAsb[160 + lane], sb);

        fa = __hadd2(fa, *(half2*)&tj.x);
        fb = __hadd2(fb, *(half2*)&tj.y);
        sa = __hadd2(sa, *(half2*)&tj.z);
        sb = __hadd2(sb, *(half2*)&tj.w);

        half2 t0 = h2tanh_(__hadd2(fa, fi2a));
        half2 t1 = h2tanh_(__hadd2(fb, fi2b));

        float2 s01 = __half22float2(sa);
        float2 s23 = __half22float2(sb);
        float u0 = ex2f(si.x + s01.x);
        float u1 = ex2f(si.y + s01.y);
        float u2 = ex2f(si.z + s23.x);
        float u3 = ex2f(si.w + s23.y);
        half2 sp01 = __floats2half2_rn(lg2f(1.f + u0), lg2f(1.f + u1));
        half2 sp23 = __floats2half2_rn(lg2f(1.f + u2), lg2f(1.f + u3));

        half2 m0 = __hfma2(t0, sp01, sp01);
        half2 m1 = __hfma2(t1, sp23, sp23);
        mx0 = __hmax2(mx0, m0);
        mx1 = __hmax2(mx1, m1);
    }

    float2 mf0 = __half22float2(mx0);
    float2 mf1 = __half22float2(mx1);

    float4 g4 = ((const float4*)(gamma + (size_t)l * CC))[lane];
    float4 b4 = ((const float4*)(beta + (size_t)l * CC))[lane];
    float4 m4 = ((const float4*)(bmean + (size_t)l * CC))[lane];
    float4 v4 = ((const float4*)(bvar + (size_t)l * CC))[lane];
    float4* H4 = (float4*)g_h;
    float4 h4 = H4[(size_t)n * 32 + lane];
    h4.x += (mf0.x * MSCALE - m4.x) * rsqrtf(v4.x + 1e-5f) * g4.x + b4.x;
    h4.y += (mf0.y * MSCALE - m4.y) * rsqrtf(v4.y + 1e-5f) * g4.y + b4.y;
    h4.z += (mf1.x * MSCALE - m4.z) * rsqrtf(v4.z + 1e-5f) * g4.z + b4.z;
    h4.w += (mf1.y * MSCALE - m4.w) * rsqrtf(v4.w + 1e-5f) * g4.w + b4.w;

    if (!last) {
        H4[(size_t)n * 32 + lane] = h4;
    } else {
        ((float4*)(out + (size_t)NN * KK))[(size_t)n * 32 + lane] = h4;
#pragma unroll
        for (int jq = 0; jq < KK; jq++) {
            float4 w = ((const float4*)linW)[jq * 32 + lane];
            float p = h4.x * w.x + h4.y * w.y + h4.z * w.z + h4.w * w.w;
#pragma unroll
            for (int d = 16; d; d >>= 1) p += __shfl_xor_sync(0xffffffffu, p, d);
            if (lane == 0) out[(size_t)n * KK + jq] = p + __ldg(linb + jq);
        }
    }
}

// ---------------- launch ----------------
extern "C" void kernel_launch(void* const* d_in, const int* in_sizes, int n_in,
                              void* d_out, int out_size) {
    const float* x       = (const float*)d_in[0];
    const int*   ei      = (const int*)d_in[1];
    const float* ea      = (const float*)d_in[2];
    const float* node_W  = (const float*)d_in[3];
    const float* node_b  = (const float*)d_in[4];
    const float* edge_W  = (const float*)d_in[5];
    const float* edge_b  = (const float*)d_in[6];
    const float* Wf      = (const float*)d_in[7];
    const float* bf      = (const float*)d_in[8];
    const float* Ws      = (const float*)d_in[9];
    const float* bs      = (const float*)d_in[10];
    const float* gamma   = (const float*)d_in[11];
    const float* beta    = (const float*)d_in[12];
    const float* bn_mean = (const float*)d_in[13];
    const float* bn_var  = (const float*)d_in[14];
    const float* lin_W   = (const float*)d_in[15];
    const float* lin_b   = (const float*)d_in[16];
    float* out = (float*)d_out;

    cudaFuncSetAttribute(k_mma, cudaFuncAttributeMaxDynamicSharedMemorySize, SMEM_MMA);

    cudaStream_t s2;
    cudaStreamCreateWithFlags(&s2, cudaStreamNonBlocking);
    cudaEvent_t evFork, evCSR;
    cudaEventCreateWithFlags(&evFork, cudaEventDisableTiming);
    cudaEventCreateWithFlags(&evCSR, cudaEventDisableTiming);

    int mgrid = (NN + 127) / 128;
    int agrid = (NN * 32 + 255) / 256;

    cudaEventRecord(evFork, 0);
    cudaStreamWaitEvent(s2, evFork, 0);

    // g_deg starts zeroed (static init on first run; k_scan1 re-zeros for replays)
    k_hist<<<(EE + 255) / 256, 256, 0, s2>>>(ei);                    // 0
    k_setup<<<FB + WB + NB, 256>>>(x, node_W, node_b, Wf, bf, Ws, bs,
                                   edge_W, edge_b);                  // 1
    k_scan1<<<SC_NB, 256, 0, s2>>>();                                // 2
    k_mma<<<mgrid, 512, SMEM_MMA>>>(0);                              // 3 (profiled)
    k_scan3<<<SC_NB, 256, 0, s2>>>();                                // 4
    k_scatter<<<(EE + 255) / 256, 256, 0, s2>>>(ei, ea);             // 5
    cudaEventRecord(evCSR, s2);

    cudaStreamWaitEvent(0, evCSR, 0);
    k_agg<<<agrid, 256>>>(gamma, beta, bn_mean, bn_var, 0, 0, lin_W, lin_b, out);

    k_mma<<<mgrid, 512, SMEM_MMA>>>(1);
    k_agg<<<agrid, 256>>>(gamma, beta, bn_mean, bn_var, 1, 0, lin_W, lin_b, out);
    k_mma<<<mgrid, 512, SMEM_MMA>>>(2);
    k_agg<<<agrid, 256>>>(gamma, beta, bn_mean, bn_var, 2, 1, lin_W, lin_b, out);
}

// round 14
// speedup vs baseline: 1.0855x; 1.0210x over previous
#include <cuda_runtime.h>
#include <cuda_fp16.h>
#include <cstdint>

#define NN 50000
#define EE 800000
#define CC 128
#define LL 3
#define KK 10

#define LOG2E 1.4426950408889634f
#define MSCALE 0.34657359027997264f  // 0.5 * ln2

// ---------------- scratch ----------------
__device__ __align__(16) float  g_h[NN * CC];
__device__ __align__(16) __half g_Ti[(size_t)NN * 256];       // interleaved [hf_i x4 | hs_i x4]
__device__ __align__(16) __half g_Tj[(size_t)NN * 256];       // interleaved [hf_j x4 | hs_j x4]
__device__ __align__(16) __half g_Bcath[LL * 512 * CC];       // quadrant order: hf_i, hs_i, hf_j, hs_j
__device__ __align__(16) float  g_AfT[LL * 6 * CC];           // x0.5
__device__ __align__(16) float  g_AsT[LL * 6 * CC];           // xlog2e
__device__ __align__(16) float  g_cf[LL * CC];
__device__ __align__(16) float  g_cs[LL * CC];
__device__ int   g_deg[NN + 1];                               // zero-init; scan1 re-zeros
__device__ int   g_off[NN + 1];
__device__ int   g_cur[NN];
__device__ __align__(16) uint4 g_edge[EE];  // {src, ea01, ea23, ea45}
__device__ int   g_bsum[64];

// ---------------- math helpers ----------------
__device__ __forceinline__ float ex2f(float x) {
    float r; asm("ex2.approx.f32 %0, %1;" : "=f"(r) : "f"(x)); return r;
}
__device__ __forceinline__ float lg2f(float x) {
    float r; asm("lg2.approx.f32 %0, %1;" : "=f"(r) : "f"(x)); return r;
}
__device__ __forceinline__ half2 h2tanh_(half2 x) {
    uint32_t xi = *(uint32_t*)&x, ri;
    asm("tanh.approx.f16x2 %0, %1;" : "=r"(ri) : "r"(xi));
    return *(half2*)&ri;
}
__device__ __forceinline__ void mma_f16(float* d, const uint32_t* a, const uint32_t* b) {
    asm volatile(
        "mma.sync.aligned.m16n8k16.row.col.f32.f16.f16.f32 "
        "{%0,%1,%2,%3}, {%4,%5,%6,%7}, {%8,%9}, {%0,%1,%2,%3};"
        : "+f"(d[0]), "+f"(d[1]), "+f"(d[2]), "+f"(d[3])
        : "r"(a[0]), "r"(a[1]), "r"(a[2]), "r"(a[3]), "r"(b[0]), "r"(b[1]));
}
__device__ __forceinline__ void ldsm_x4(uint32_t& r0, uint32_t& r1, uint32_t& r2, uint32_t& r3,
                                        uint32_t saddr) {
    asm volatile("ldmatrix.sync.aligned.m8n8.x4.shared.b16 {%0,%1,%2,%3}, [%4];"
                 : "=r"(r0), "=r"(r1), "=r"(r2), "=r"(r3) : "r"(saddr));
}
__device__ __forceinline__ void ldsm_x2(uint32_t& r0, uint32_t& r1, uint32_t saddr) {
    asm volatile("ldmatrix.sync.aligned.m8n8.x2.shared.b16 {%0,%1}, [%2];"
                 : "=r"(r0), "=r"(r1) : "r"(saddr));
}
#define CP_COMMIT() asm volatile("cp.async.commit_group;")
#define CP_WAIT1()  asm volatile("cp.async.wait_group 1;")
#define CP_WAIT0()  asm volatile("cp.async.wait_group 0;")

// ---------------- fused setup: fold | bprep(half, reordered) | node_encode ----------------
#define FB 21
#define WB 768
#define NB 25000
__global__ void k_setup(const float* __restrict__ x, const float* __restrict__ nW,
                        const float* __restrict__ nb,
                        const float* __restrict__ Wf, const float* __restrict__ bf,
                        const float* __restrict__ Ws, const float* __restrict__ bs,
                        const float* __restrict__ eW, const float* __restrict__ eb) {
    int b = blockIdx.x, tid = threadIdx.x;
    if (b < FB) {
        int t = b * 256 + tid;
        if (t >= LL * CC * 14) return;
        int l = t / (CC * 14);
        int r = t % (CC * 14);
        int c = r / 14, kk = r % 14;
        const float* rf = Wf + ((size_t)(l * CC + c) * 3 * CC) + 2 * CC;
        const float* rs = Ws + ((size_t)(l * CC + c) * 3 * CC) + 2 * CC;
        if (kk < 6) {
            float s = 0.f;
            for (int j = 0; j < CC; j++) s = fmaf(rf[j], eW[j * 6 + kk], s);
            g_AfT[l * 6 * CC + kk * CC + c] = s * 0.5f;
        } else if (kk < 12) {
            int k = kk - 6;
            float s = 0.f;
            for (int j = 0; j < CC; j++) s = fmaf(rs[j], eW[j * 6 + k], s);
            g_AsT[l * 6 * CC + k * CC + c] = s * LOG2E;
        } else if (kk == 12) {
            float s = bf[l * CC + c];
            for (int j = 0; j < CC; j++) s = fmaf(rf[j], eb[j], s);
            g_cf[l * CC + c] = s * 0.5f;
        } else {
            float s = bs[l * CC + c];
            for (int j = 0; j < CC; j++) s = fmaf(rs[j], eb[j], s);
            g_cs[l * CC + c] = s * LOG2E;
        }
    } else if (b < FB + WB) {
        int t = (b - FB) * 256 + tid;
        int l = t / (512 * CC);
        int r = t % (512 * CC);
        int n = r / CC, k = r % CC;
        int q = n >> 7, c = n & 127;
        // quadrant order: 0=hf_i(Wfi) 1=hs_i(Wsi) 2=hf_j(Wfj) 3=hs_j(Wsj)
        const float* base = (q & 1) ? Ws : Wf;
        float scale = (q & 1) ? LOG2E : 0.5f;
        float v = base[(size_t)(l * CC + c) * 3 * CC + ((q >> 1) ? CC : 0) + k] * scale;
        g_Bcath[t] = __float2half_rn(v);
    } else {
        int i = (b - FB - WB) * 256 + tid;
        int n = i / CC, c = i % CC;
        const float* xr = x + (size_t)n * 7;
        const float* wr = nW + (size_t)c * 7;
        float acc = nb[c];
#pragma unroll
        for (int k = 0; k < 7; k++) acc = fmaf(xr[k], wr[k], acc);
        g_h[i] = acc;
    }
}

// ---------------- CSR build (per-block int32/int64 self-detect) ----------------
__global__ void k_hist(const int* __restrict__ ei32) {
    int e = blockIdx.x * blockDim.x + threadIdx.x;
    int hi = (e < EE) ? ei32[2 * e + 1] : 0;
    int any32 = __syncthreads_or(hi != 0);
    if (e >= EE) return;
    int dst;
    if (any32) dst = ei32[EE + e];
    else       dst = (int)(((const long long*)ei32)[EE + e]);
    atomicAdd(&g_deg[dst], 1);
}

#define SC_NB 50
__global__ void __launch_bounds__(256) k_scan1() {
    __shared__ int sw[8];
    int b = blockIdx.x, tid = threadIdx.x, lane = tid & 31, wid = tid >> 5;
    int base = b * 1024 + tid * 4;
    int v[4];
    int run = 0;
#pragma unroll
    for (int i = 0; i < 4; i++) {
        int idx = base + i;
        int t = 0;
        if (idx <= NN) {
            t = g_deg[idx];
            g_deg[idx] = 0;
        }
        v[i] = run;
        run += t;
    }
    int incl = run;
#pragma unroll
    for (int d = 1; d < 32; d <<= 1) {
        int y = __shfl_up_sync(0xffffffffu, incl, d);
        if (lane >= d) incl += y;
    }
    if (lane == 31) sw[wid] = incl;
    __syncthreads();
    if (tid < 8) {
        int w = sw[tid];
        int wi = w;
#pragma unroll
        for (int d = 1; d < 8; d <<= 1) {
            int y = __shfl_up_sync(0xffu, wi, d);
            if (tid >= d) wi += y;
        }
        sw[tid] = wi - w;
        if (tid == 7) g_bsum[b] = wi;
    }
    __syncthreads();
    int off0 = sw[wid] + (incl - run);
#pragma unroll
    for (int i = 0; i < 4; i++) {
        int idx = base + i;
        if (idx <= NN) g_off[idx] = off0 + v[i];
    }
}

__global__ void __launch_bounds__(256) k_scan3() {
    __shared__ int wsum[2];
    int b = blockIdx.x, tid = threadIdx.x;
    if (tid < 64) {
        int v = (tid < b) ? g_bsum[tid] : 0;
#pragma unroll
        for (int d = 16; d; d >>= 1) v += __shfl_xor_sync(0xffffffffu, v, d);
        if ((tid & 31) == 0) wsum[tid >> 5] = v;
    }
    __syncthreads();
    int add = wsum[0] + wsum[1];
#pragma unroll
    for (int i = 0; i < 4; i++) {
        int idx = b * 1024 + tid * 4 + i;
        if (idx <= NN) {
            int o = g_off[idx] + add;
            g_off[idx] = o;
            if (idx < NN) g_cur[idx] = o;
        }
    }
}

__global__ void k_scatter(const int* __restrict__ ei32, const float* __restrict__ ea) {
    int e = blockIdx.x * blockDim.x + threadIdx.x;
    int hi = (e < EE) ? ei32[2 * e + 1] : 0;
    int any32 = __syncthreads_or(hi != 0);
    if (e >= EE) return;
    int src, dst;
    if (any32) {
        src = ei32[e];
        dst = ei32[EE + e];
    } else {
        const long long* ll = (const long long*)ei32;
        src = (int)ll[e];
        dst = (int)ll[EE + e];
    }
    int pos = atomicAdd(&g_cur[dst], 1);
    const float* a = ea + (size_t)e * 6;
    half2 x01 = __floats2half2_rn(a[0], a[1]);
    half2 x23 = __floats2half2_rn(a[2], a[3]);
    half2 x45 = __floats2half2_rn(a[4], a[5]);
    uint4 u;
    u.x = (uint32_t)src;
    u.y = *(uint32_t*)&x01;
    u.z = *(uint32_t*)&x23;
    u.w = *(uint32_t*)&x45;
    g_edge[pos] = u;
}

// ---------------- fp16 mma GEMM: T = h @ Bcath^T (M=NN, N=512, K=128) ----------------
// 512 threads, 16 warps, 4x4 warp grid of 32x32 tiles, ldmatrix + smem-staged epilogue.
#define LDH2 68
#define TILE_W (128 * LDH2)              // one 128-row tile in uint32 units
#define SMEM_MMA (5 * TILE_W * 4)

__device__ __forceinline__ void issue_b(const __half* __restrict__ Bsrc, uint32_t* sBuf, int tid) {
#pragma unroll
    for (int i = 0; i < 4; i++) {
        int idx = tid + i * 512;
        int row = idx >> 4, c8 = (idx & 15) << 3;
        uint32_t sa = (uint32_t)__cvta_generic_to_shared((const char*)(sBuf + row * LDH2) + c8 * 2);
        asm volatile("cp.async.ca.shared.global [%0], [%1], 16;"
                     :: "r"(sa), "l"(Bsrc + (size_t)row * CC + c8));
    }
    CP_COMMIT();
}

__device__ __forceinline__ void mma_compute(uint32_t aBase, uint32_t bBase,
                                            float acc[2][4][4],
                                            int wm, int wn, int lane) {
#pragma unroll
    for (int mi = 0; mi < 2; mi++)
#pragma unroll
        for (int ni = 0; ni < 4; ni++)
#pragma unroll
            for (int p = 0; p < 4; p++) acc[mi][ni][p] = 0.f;

    uint32_t aAddr[2], bAddr[4];
#pragma unroll
    for (int mi = 0; mi < 2; mi++)
        aAddr[mi] = aBase + (((wm + mi * 16 + (lane & 15)) * LDH2 + ((lane >> 4) << 2)) << 2);
#pragma unroll
    for (int ni = 0; ni < 4; ni++)
        bAddr[ni] = bBase + (((wn + ni * 8 + (lane & 7)) * LDH2 + (((lane >> 3) & 1) << 2)) << 2);

#pragma unroll
    for (int ks = 0; ks < 8; ks++) {
        uint32_t a[2][4];
#pragma unroll
        for (int mi = 0; mi < 2; mi++) {
            ldsm_x4(a[mi][0], a[mi][1], a[mi][2], a[mi][3], aAddr[mi]);
            aAddr[mi] += 32;
        }
        uint32_t b[4][2];
#pragma unroll
        for (int ni = 0; ni < 4; ni++) {
            ldsm_x2(b[ni][0], b[ni][1], bAddr[ni]);
            bAddr[ni] += 32;
        }
#pragma unroll
        for (int mi = 0; mi < 2; mi++)
#pragma unroll
            for (int ni = 0; ni < 4; ni++)
                mma_f16(acc[mi][ni], a[mi], b[ni]);
    }
}

// stage acc (natural column order, half2 slots) into padded smem tile: conflict-free
__device__ __forceinline__ void stage_acc(float acc[2][4][4], uint32_t* st,
                                          int wm, int wn, int gr, int tg) {
#pragma unroll
    for (int mi = 0; mi < 2; mi++) {
        int r0 = wm + mi * 16 + gr;
#pragma unroll
        for (int ni = 0; ni < 4; ni++) {
            int slot = ((wn + ni * 8) >> 1) + tg;
            half2 h0 = __floats2half2_rn(acc[mi][ni][0], acc[mi][ni][1]);
            half2 h1 = __floats2half2_rn(acc[mi][ni][2], acc[mi][ni][3]);
            st[r0 * LDH2 + slot] = *(uint32_t*)&h0;
            st[(r0 + 8) * LDH2 + slot] = *(uint32_t*)&h1;
        }
    }
}

// coalesced copy: interleave [f x4 | s x4] per 8-half group, full 512B rows
__device__ __forceinline__ void copy_out(__half* dst, const uint32_t* stF, const uint32_t* stS,
                                         int bm, int tid) {
#pragma unroll
    for (int i = 0; i < 8; i++) {
        int idx = tid + i * 512;
        int r = idx >> 5, g = idx & 31;
        if (bm + r < NN) {
            uint2 f = *(const uint2*)(stF + r * LDH2 + 2 * g);
            uint2 s = *(const uint2*)(stS + r * LDH2 + 2 * g);
            uint4 o = make_uint4(f.x, f.y, s.x, s.y);
            *(uint4*)(dst + (size_t)(bm + r) * 256 + g * 8) = o;
        }
    }
}

__global__ void __launch_bounds__(512) k_mma(int l) {
    extern __shared__ uint32_t smem_u[];
    uint32_t* sA  = smem_u;
    uint32_t* sB0 = smem_u + TILE_W;
    uint32_t* sB1 = smem_u + 2 * TILE_W;
    uint32_t* stF = smem_u + 3 * TILE_W;
    uint32_t* stS = smem_u + 4 * TILE_W;
    const int tid = threadIdx.x;
    const int wid = tid >> 5, lane = tid & 31;
    const int bm = blockIdx.x * 128;
    const int wm = (wid >> 2) * 32, wn = (wid & 3) * 32;
    const int gr = lane >> 2, tg = lane & 3;

    uint32_t sbase = (uint32_t)__cvta_generic_to_shared(smem_u);
    uint32_t aBase = sbase;
    uint32_t b0Base = sbase + TILE_W * 4;
    uint32_t b1Base = sbase + 2 * TILE_W * 4;

    const __half* Bl = g_Bcath + (size_t)l * 512 * CC;
    issue_b(Bl + 0 * 128 * CC, sB0, tid);   // hf_i
    issue_b(Bl + 1 * 128 * CC, sB1, tid);   // hs_i

    // A load + f16 convert (once)
#pragma unroll
    for (int i = 0; i < 8; i++) {
        int idx = tid + i * 512;
        int row = idx >> 5;
        int col2 = (idx & 31) << 1;
        float4 v = make_float4(0.f, 0.f, 0.f, 0.f);
        if (bm + row < NN) v = *(const float4*)(g_h + (size_t)(bm + row) * CC + (col2 << 1));
        half2 h0 = __floats2half2_rn(v.x, v.y);
        half2 h1 = __floats2half2_rn(v.z, v.w);
        uint2 pk = make_uint2(*(uint32_t*)&h0, *(uint32_t*)&h1);
        *(uint2*)(sA + row * LDH2 + col2) = pk;
    }

    float acc[2][4][4];

    CP_WAIT1(); __syncthreads();
    mma_compute(aBase, b0Base, acc, wm, wn, lane);   // hf_i
    stage_acc(acc, stF, wm, wn, gr, tg);
    __syncthreads();
    issue_b(Bl + 2 * 128 * CC, sB0, tid);            // hf_j -> buf0

    CP_WAIT1(); __syncthreads();
    mma_compute(aBase, b1Base, acc, wm, wn, lane);   // hs_i
    stage_acc(acc, stS, wm, wn, gr, tg);
    __syncthreads();
    copy_out(g_Ti, stF, stS, bm, tid);
    issue_b(Bl + 3 * 128 * CC, sB1, tid);            // hs_j -> buf1

    CP_WAIT1(); __syncthreads();
    mma_compute(aBase, b0Base, acc, wm, wn, lane);   // hf_j
    stage_acc(acc, stF, wm, wn, gr, tg);

    CP_WAIT0(); __syncthreads();
    mma_compute(aBase, b1Base, acc, wm, wn, lane);   // hs_j
    stage_acc(acc, stS, wm, wn, gr, tg);
    __syncthreads();
    copy_out(g_Tj, stF, stS, bm, tid);
}

// ---------------- per-layer aggregation + BN + residual (+ fused head on last) ----------------
__global__ void __launch_bounds__(256) k_agg(const float* __restrict__ gamma,
                                             const float* __restrict__ beta,
                                             const float* __restrict__ bmean,
                                             const float* __restrict__ bvar,
                                             int l, int last,
                                             const float* __restrict__ linW,
                                             const float* __restrict__ linb,
                                             float* __restrict__ out) {
    __shared__ half2 sAfa[192], sAfb[192], sAsa[192], sAsb[192];
    __shared__ float4 sC[64];
    int tid = threadIdx.x;
    if (tid < 192) {
        int k = tid >> 5, ln = tid & 31;
        const float* Af = g_AfT + (size_t)l * 6 * CC + k * CC + 4 * ln;
        const float* As_ = g_AsT + (size_t)l * 6 * CC + k * CC + 4 * ln;
        sAfa[tid] = __floats2half2_rn(Af[0], Af[1]);
        sAfb[tid] = __floats2half2_rn(Af[2], Af[3]);
        sAsa[tid] = __floats2half2_rn(As_[0], As_[1]);
        sAsb[tid] = __floats2half2_rn(As_[2], As_[3]);
    }
    if (tid < 32)
        sC[tid] = ((const float4*)(g_cf + (size_t)l * CC))[tid];
    else if (tid < 64)
        sC[tid] = ((const float4*)(g_cs + (size_t)l * CC))[tid - 32];
    __syncthreads();

    int lane = tid & 31;
    int n = (blockIdx.x * 256 + tid) >> 5;
    if (n >= NN) return;

    uint4 ti = ((const uint4*)g_Ti)[(size_t)n * 32 + lane];
    float4 c0 = sC[lane], c1 = sC[32 + lane];
    half2 fi2a = __hadd2(*(half2*)&ti.x, __floats2half2_rn(c0.x, c0.y));
    half2 fi2b = __hadd2(*(half2*)&ti.y, __floats2half2_rn(c0.z, c0.w));
    float2 sia = __half22float2(*(half2*)&ti.z);
    float2 sib = __half22float2(*(half2*)&ti.w);
    float4 si = make_float4(sia.x + c1.x, sia.y + c1.y, sib.x + c1.z, sib.y + c1.w);

    const uint4* Tj4 = (const uint4*)g_Tj;

    half2 mx0 = __float2half2_rn(0.f);
    half2 mx1 = mx0;
    int beg = g_off[n], end = g_off[n + 1];

    uint4 e0, e1, tj0;
    if (beg < end) {
        e0 = g_edge[beg];
        tj0 = Tj4[(size_t)e0.x * 32 + lane];
    }
    if (beg + 1 < end) e1 = g_edge[beg + 1];

    for (int j = beg; j < end; j++) {
        uint4 ec = e0;
        uint4 tj = tj0;
        if (j + 1 < end) {
            tj0 = Tj4[(size_t)e1.x * 32 + lane];
            e0 = e1;
        }
        if (j + 2 < end) e1 = g_edge[j + 2];

        half2 p01 = *(half2*)&ec.y;
        half2 p23 = *(half2*)&ec.z;
        half2 p45 = *(half2*)&ec.w;
        half2 a0 = __low2half2(p01), a1 = __high2half2(p01);
        half2 a2 = __low2half2(p23), a3 = __high2half2(p23);
        half2 a4 = __low2half2(p45), a5 = __high2half2(p45);

        half2 fa = __hmul2(a0, sAfa[lane]);
        half2 fb = __hmul2(a0, sAfb[lane]);
        half2 sa = __hmul2(a0, sAsa[lane]);
        half2 sb = __hmul2(a0, sAsb[lane]);
        fa = __hfma2(a1, sAfa[32 + lane], fa);  fb = __hfma2(a1, sAfb[32 + lane], fb);
        sa = __hfma2(a1, sAsa[32 + lane], sa);  sb = __hfma2(a1, sAsb[32 + lane], sb);
        fa = __hfma2(a2, sAfa[64 + lane], fa);  fb = __hfma2(a2, sAfb[64 + lane], fb);
        sa = __hfma2(a2, sAsa[64 + lane], sa);  sb = __hfma2(a2, sAsb[64 + lane], sb);
        fa = __hfma2(a3, sAfa[96 + lane], fa);  fb = __hfma2(a3, sAfb[96 + lane], fb);
        sa = __hfma2(a3, sAsa[96 + lane], sa);  sb = __hfma2(a3, sAsb[96 + lane], sb);
        fa = __hfma2(a4, sAfa[128 + lane], fa); fb = __hfma2(a4, sAfb[128 + lane], fb);
        sa = __hfma2(a4, sAsa[128 + lane], sa); sb = __hfma2(a4, sAsb[128 + lane], sb);
        fa = __hfma2(a5, sAfa[160 + lane], fa); fb = __hfma2(a5, sAfb[160 + lane], fb);
        sa = __hfma2(a5, sAsa[160 + lane], sa); sb = __hfma2(a5, sAsb[160 + lane], sb);

        fa = __hadd2(fa, *(half2*)&tj.x);
        fb = __hadd2(fb, *(half2*)&tj.y);
        sa = __hadd2(sa, *(half2*)&tj.z);
        sb = __hadd2(sb, *(half2*)&tj.w);

        half2 t0 = h2tanh_(__hadd2(fa, fi2a));
        half2 t1 = h2tanh_(__hadd2(fb, fi2b));

        float2 s01 = __half22float2(sa);
        float2 s23 = __half22float2(sb);
        float u0 = ex2f(si.x + s01.x);
        float u1 = ex2f(si.y + s01.y);
        float u2 = ex2f(si.z + s23.x);
        float u3 = ex2f(si.w + s23.y);
        half2 sp01 = __floats2half2_rn(lg2f(1.f + u0), lg2f(1.f + u1));
        half2 sp23 = __floats2half2_rn(lg2f(1.f + u2), lg2f(1.f + u3));

        half2 m0 = __hfma2(t0, sp01, sp01);
        half2 m1 = __hfma2(t1, sp23, sp23);
        mx0 = __hmax2(mx0, m0);
        mx1 = __hmax2(mx1, m1);
    }

    float2 mf0 = __half22float2(mx0);
    float2 mf1 = __half22float2(mx1);

    float4 g4 = ((const float4*)(gamma + (size_t)l * CC))[lane];
    float4 b4 = ((const float4*)(beta + (size_t)l * CC))[lane];
    float4 m4 = ((const float4*)(bmean + (size_t)l * CC))[lane];
    float4 v4 = ((const float4*)(bvar + (size_t)l * CC))[lane];
    float4* H4 = (float4*)g_h;
    float4 h4 = H4[(size_t)n * 32 + lane];
    h4.x += (mf0.x * MSCALE - m4.x) * rsqrtf(v4.x + 1e-5f) * g4.x + b4.x;
    h4.y += (mf0.y * MSCALE - m4.y) * rsqrtf(v4.y + 1e-5f) * g4.y + b4.y;
    h4.z += (mf1.x * MSCALE - m4.z) * rsqrtf(v4.z + 1e-5f) * g4.z + b4.z;
    h4.w += (mf1.y * MSCALE - m4.w) * rsqrtf(v4.w + 1e-5f) * g4.w + b4.w;

    if (!last) {
        H4[(size_t)n * 32 + lane] = h4;
    } else {
        ((float4*)(out + (size_t)NN * KK))[(size_t)n * 32 + lane] = h4;
#pragma unroll
        for (int jq = 0; jq < KK; jq++) {
            float4 w = ((const float4*)linW)[jq * 32 + lane];
            float p = h4.x * w.x + h4.y * w.y + h4.z * w.z + h4.w * w.w;
#pragma unroll
            for (int d = 16; d; d >>= 1) p += __shfl_xor_sync(0xffffffffu, p, d);
            if (lane == 0) out[(size_t)n * KK + jq] = p + __ldg(linb + jq);
        }
    }
}

// ---------------- launch ----------------
extern "C" void kernel_launch(void* const* d_in, const int* in_sizes, int n_in,
                              void* d_out, int out_size) {
    const float* x       = (const float*)d_in[0];
    const int*   ei      = (const int*)d_in[1];
    const float* ea      = (const float*)d_in[2];
    const float* node_W  = (const float*)d_in[3];
    const float* node_b  = (const float*)d_in[4];
    const float* edge_W  = (const float*)d_in[5];
    const float* edge_b  = (const float*)d_in[6];
    const float* Wf      = (const float*)d_in[7];
    const float* bf      = (const float*)d_in[8];
    const float* Ws      = (const float*)d_in[9];
    const float* bs      = (const float*)d_in[10];
    const float* gamma   = (const float*)d_in[11];
    const float* beta    = (const float*)d_in[12];
    const float* bn_mean = (const float*)d_in[13];
    const float* bn_var  = (const float*)d_in[14];
    const float* lin_W   = (const float*)d_in[15];
    const float* lin_b   = (const float*)d_in[16];
    float* out = (float*)d_out;

    cudaFuncSetAttribute(k_mma, cudaFuncAttributeMaxDynamicSharedMemorySize, SMEM_MMA);

    cudaStream_t s2;
    cudaStreamCreateWithFlags(&s2, cudaStreamNonBlocking);
    cudaEvent_t evFork, evCSR;
    cudaEventCreateWithFlags(&evFork, cudaEventDisableTiming);
    cudaEventCreateWithFlags(&evCSR, cudaEventDisableTiming);

    int mgrid = (NN + 127) / 128;
    int agrid = (NN * 32 + 255) / 256;

    cudaEventRecord(evFork, 0);
    cudaStreamWaitEvent(s2, evFork, 0);

    k_hist<<<(EE + 255) / 256, 256, 0, s2>>>(ei);                    // 0
    k_setup<<<FB + WB + NB, 256>>>(x, node_W, node_b, Wf, bf, Ws, bs,
                                   edge_W, edge_b);                  // 1
    k_scan1<<<SC_NB, 256, 0, s2>>>();                                // 2
    k_mma<<<mgrid, 512, SMEM_MMA>>>(0);                              // 3 (profiled)
    k_scan3<<<SC_NB, 256, 0, s2>>>();                                // 4
    k_scatter<<<(EE + 255) / 256, 256, 0, s2>>>(ei, ea);             // 5
    cudaEventRecord(evCSR, s2);

    cudaStreamWaitEvent(0, evCSR, 0);
    k_agg<<<agrid, 256>>>(gamma, beta, bn_mean, bn_var, 0, 0, lin_W, lin_b, out);

    k_mma<<<mgrid, 512, SMEM_MMA>>>(1);
    k_agg<<<agrid, 256>>>(gamma, beta, bn_mean, bn_var, 1, 0, lin_W, lin_b, out);
    k_mma<<<mgrid, 512, SMEM_MMA>>>(2);
    k_agg<<<agrid, 256>>>(gamma, beta, bn_mean, bn_var, 2, 1, lin_W, lin_b, out);
}